// round 17
// baseline (speedup 1.0000x reference)
#include <cuda_runtime.h>

// MaxPool2d k=2 s=2 valid, (32,64,224,224) fp32 -> (32,64,112,112).
// R16 = R12 body with WARP-ALIGNED column tiling. R12's GROUPS_W=56 is not a
// multiple of 32, so ~4/7 warps straddle the column-wrap boundary and their
// LDG.128 instructions span two discontiguous segments. Here the column
// dimension is padded to 64: g = idx & 63, lanes with g>=56 exit early
// (12.5% idle lanes -> issue slots only, no bandwidth). Every active warp
// load is now exactly one contiguous 512 B segment; the mod-56 becomes
// shift/mask. Otherwise identical to the confirmed-best R12: one thread =
// 2 out rows x 2 out cols, 4 front-batched lane-consecutive LDG.128,
// 2 coalesced STG.64, plain cache ops.

#define NC_TOTAL   2048              // 32 * 64
#define IH         224
#define IW         224
#define OH         112
#define OW         112
#define IN_PLANE   (IH * IW)         // 50176
#define OUT_PLANE  (OH * OW)         // 12544
#define GROUPS_W   (IW / 4)          // 56 real float4 columns
#define GW_PAD     64                // padded to warp multiple
#define ROWPAIRS   (OH / 2)          // 56 output-row pairs
#define TOTAL_THREADS (NC_TOTAL * ROWPAIRS * GW_PAD)   // 7,340,032

__global__ __launch_bounds__(256)
void maxpool2d_k2s2_warpal_kernel(const float* __restrict__ in, float* __restrict__ out) {
    int idx = blockIdx.x * blockDim.x + threadIdx.x;
    if (idx >= TOTAL_THREADS) return;

    int g = idx & (GW_PAD - 1);          // float4 column, warp-aligned tiling
    if (g >= GROUPS_W) return;           // padded lanes idle
    int t   = idx >> 6;                  // (nc, ohp) index
    int ohp = t % ROWPAIRS;
    int nc  = t / ROWPAIRS;

    const int rstep = IW / 4;            // 56 float4 per input row
    const float4* base = reinterpret_cast<const float4*>(
        in + (size_t)nc * IN_PLANE + (size_t)(ohp * 4) * IW) + g;

    // 4 front-batched, independent, per-instruction fully coalesced LDG.128;
    // no warp straddles a row boundary now.
    float4 a = base[0 * rstep];          // input row 4*ohp
    float4 b = base[1 * rstep];          // input row 4*ohp+1
    float4 c = base[2 * rstep];          // input row 4*ohp+2
    float4 d = base[3 * rstep];          // input row 4*ohp+3

    float2 o0, o1;
    o0.x = fmaxf(fmaxf(a.x, a.y), fmaxf(b.x, b.y));
    o0.y = fmaxf(fmaxf(a.z, a.w), fmaxf(b.z, b.w));
    o1.x = fmaxf(fmaxf(c.x, c.y), fmaxf(d.x, d.y));
    o1.y = fmaxf(fmaxf(c.z, c.w), fmaxf(d.z, d.w));

    float2* orow0 = reinterpret_cast<float2*>(
        out + (size_t)nc * OUT_PLANE + (size_t)(ohp * 2) * OW) + g;
    float2* orow1 = orow0 + (OW / 2);    // next output row = 56 float2

    orow0[0] = o0;
    orow1[0] = o1;
}

extern "C" void kernel_launch(void* const* d_in, const int* in_sizes, int n_in,
                              void* d_out, int out_size) {
    const float* in = (const float*)d_in[0];
    float* out = (float*)d_out;
    int blocks = (TOTAL_THREADS + 255) / 256;   // 28672
    maxpool2d_k2s2_warpal_kernel<<<blocks, 256>>>(in, out);
}